// round 3
// baseline (speedup 1.0000x reference)
#include <cuda_runtime.h>
#include <math.h>

// Problem constants
#define BDIM 256
#define RT   12            // rows per tile
#define DD   256           // state dim
#define HH   100           // hidden
#define KF   257           // features = 1 + D
#define KP   260           // padded feature length (float4; phase banks 4l mod 32 distinct)
#define W2S  108           // W2^T row stride (phase banks 12l mod 32 distinct -> conflict-free)
#define HSS  100           // h tile row stride (broadcast loads, multiple of 4)

// smem layout (in floats)
#define OFF_W1T 0                      // 100*260 = 26000
#define OFF_W2T (OFF_W1T + HH*KP)      // 26000 + 27648 -> 53648
#define OFF_ZS  (OFF_W2T + DD*W2S)     // 53648 + 3120  -> 56768
#define OFF_HS  (OFF_ZS  + RT*KP)      // 56768 + 1200  -> 57968
#define OFF_WR  (OFF_HS  + RT*HSS)     // 57968 + 96    -> 58064
#define OFF_SC  (OFF_WR  + 8*RT)       // 58064 + 12    -> 58076
#define SMEM_FLOATS (OFF_SC + RT)      // 58076 floats = 232304 bytes (< 232448 opt-in cap)

__global__ void __launch_bounds__(BDIM, 1)
cvx_policy_kernel(const float* __restrict__ z, const float* __restrict__ t,
                  const float* __restrict__ W1, const float* __restrict__ b1,
                  const float* __restrict__ W2, const float* __restrict__ b2,
                  float* __restrict__ out, int B)
{
    extern __shared__ float sm[];
    float* W1T = sm + OFF_W1T;   // [HH][KP]   W1T[j][k] = W1[k][j]
    float* W2T = sm + OFF_W2T;   // [DD][W2S]  W2T[c][k] = W2[k][c]
    float* ZS  = sm + OFF_ZS;    // [RT][KP]   features per row
    float* HS  = sm + OFF_HS;    // [RT][HSS]  tanh hidden
    float* WR  = sm + OFF_WR;    // [8][RT]    per-warp r2 partials
    float* SC  = sm + OFF_SC;    // [RT]       scales

    const int tid  = threadIdx.x;
    const int lane = tid & 31;
    const int warp = tid >> 5;
    const int j    = tid & 127;   // hidden unit for layer 1
    const int half = tid >> 7;    // k-range half for layer 1

    // ---- load W1 transposed: global [257][100] row-major -> W1T[j][k]
    for (int i = tid; i < KF * HH; i += BDIM) {
        int k = i / HH, jj = i % HH;
        W1T[jj * KP + k] = W1[i];
    }
    // zero-pad k = 257..259 so padded chunks contribute 0
    for (int i = tid; i < HH * (KP - KF); i += BDIM) {
        int jj = i / (KP - KF), kk = KF + i % (KP - KF);
        W1T[jj * KP + kk] = 0.f;
    }
    // ---- load W2 transposed: global [100][256] -> W2T[c][k]
    for (int i = tid; i < HH * DD; i += BDIM) {
        int k = i / DD, c = i % DD;
        W2T[c * W2S + k] = W2[i];
    }
    // zero-pad ZS columns 257..259 once (never overwritten by tile loads)
    if (tid < RT * (KP - KF)) {
        int r = tid / (KP - KF), kk = KF + tid % (KP - KF);
        ZS[r * KP + kk] = 0.f;
    }

    const float b1j = (j < HH) ? b1[j] : 0.f;
    const float b2c = b2[tid];

    const int nTiles = (B + RT - 1) / RT;
    for (int tile = blockIdx.x; tile < nTiles; tile += gridDim.x) {
        const int row0 = tile * RT;
        const int rows = min(RT, B - row0);

        __syncthreads();   // weights ready / previous-tile consumers done

        // ---- stage features: ZS[r][0] = t, ZS[r][1..256] = z row (coalesced)
        for (int i = tid; i < rows * DD; i += BDIM) {
            int r = i >> 8, c = i & 255;
            ZS[r * KP + 1 + c] = z[(size_t)(row0 + r) * DD + c];
        }
        if (tid < rows) ZS[tid * KP] = t[row0 + tid];
        __syncthreads();

        // ---- layer 1: each (j, half) thread accumulates half the K range
        float acc[RT];
        #pragma unroll
        for (int r = 0; r < RT; r++) acc[r] = 0.f;
        if (j < HH) {
            const int c0 = (half == 0) ? 0  : 33;
            const int c1 = (half == 0) ? 33 : 65;   // 65 float4 chunks total
            const float4* w4 = (const float4*)(W1T + j * KP);
            for (int ch = c0; ch < c1; ch++) {
                float4 w = w4[ch];
                #pragma unroll
                for (int r = 0; r < RT; r++) {
                    float4 zv = ((const float4*)(ZS + r * KP))[ch];  // broadcast
                    acc[r] += w.x * zv.x + w.y * zv.y + w.z * zv.z + w.w * zv.w;
                }
            }
        }
        // combine halves, bias, tanh -> HS
        if (half == 1 && j < HH) {
            #pragma unroll
            for (int r = 0; r < RT; r++) HS[r * HSS + j] = acc[r];
        }
        __syncthreads();
        if (half == 0 && j < HH) {
            #pragma unroll
            for (int r = 0; r < RT; r++)
                HS[r * HSS + j] = tanhf(acc[r] + HS[r * HSS + j] + b1j);
        }
        __syncthreads();

        // ---- layer 2: thread owns output column c = tid
        float p[RT];
        #pragma unroll
        for (int r = 0; r < RT; r++) p[r] = b2c;
        {
            const float4* w4 = (const float4*)(W2T + tid * W2S);
            for (int ch = 0; ch < HH / 4; ch++) {   // 25 chunks, exactly 100
                float4 w = w4[ch];
                #pragma unroll
                for (int r = 0; r < RT; r++) {
                    float4 hv = ((const float4*)(HS + r * HSS))[ch];  // broadcast
                    p[r] += w.x * hv.x + w.y * hv.y + w.z * hv.z + w.w * hv.w;
                }
            }
        }

        // ---- r2 = sum_c p^2 : warp tree + cross-warp via smem
        #pragma unroll
        for (int r = 0; r < RT; r++) {
            float v = p[r] * p[r];
            v += __shfl_xor_sync(0xffffffffu, v, 16);
            v += __shfl_xor_sync(0xffffffffu, v, 8);
            v += __shfl_xor_sync(0xffffffffu, v, 4);
            v += __shfl_xor_sync(0xffffffffu, v, 2);
            v += __shfl_xor_sync(0xffffffffu, v, 1);
            if (lane == 0) WR[warp * RT + r] = v;
        }
        __syncthreads();

        // ---- LambertW Newton + scale (12 threads)
        if (tid < RT) {
            float r2 = 0.f;
            #pragma unroll
            for (int w = 0; w < 8; w++) r2 += WR[w * RT + tid];
            float wv = log1pf(r2);
            #pragma unroll
            for (int it = 0; it < 10; it++) {
                float ew = __expf(wv);
                wv = wv - (wv * ew - r2) / ((1.f + wv) * ew);
            }
            wv = fmaxf(wv, 0.f);
            float tn = sqrtf(wv);
            float rr = sqrtf(r2);
            SC[tid] = (rr > 1e-12f) ? tn / fmaxf(rr, 1e-12f) : 1.0f;
        }
        __syncthreads();

        // ---- store u* = -scale * p  (coalesced: c = tid)
        for (int r = 0; r < rows; r++)
            out[(size_t)(row0 + r) * DD + tid] = -SC[r] * p[r];
    }
}

extern "C" void kernel_launch(void* const* d_in, const int* in_sizes, int n_in,
                              void* d_out, int out_size)
{
    const float* z  = (const float*)d_in[0];
    const float* t  = (const float*)d_in[1];
    const float* W1 = (const float*)d_in[2];
    const float* b1 = (const float*)d_in[3];
    const float* W2 = (const float*)d_in[4];
    const float* b2 = (const float*)d_in[5];
    float* out = (float*)d_out;
    const int B = in_sizes[1];   // t has B elements

    // Unconditional (no static guards allowed): idempotent, host-side, cheap.
    cudaFuncSetAttribute(cvx_policy_kernel,
                         cudaFuncAttributeMaxDynamicSharedMemorySize,
                         SMEM_FLOATS * sizeof(float));
    cvx_policy_kernel<<<148, BDIM, SMEM_FLOATS * sizeof(float)>>>(
        z, t, W1, b1, W2, b2, out, B);
}

// round 4
// speedup vs baseline: 2.5526x; 2.5526x over previous
#include <cuda_runtime.h>
#include <cuda_bf16.h>
#include <math.h>
#include <stdint.h>

// Shapes (fixed by dataset): B=131072, D=256, H=100
#define BMAX 131072
#define DD   256
#define HH   100
#define MT   64            // batch rows per tile

// Kernel 1 (layer 1): K = 257 -> pad 272 (17 k-chunks), N = 100 -> pad 112 (14 n-chunks)
#define K1   272
#define K1C  17
#define XSTR 280           // smem row stride (bf16): 140 words -> conflict-free frag loads
#define N1   112

// Kernel 2 (layer 2): K = 112 (7 k-chunks), N = 256 (32 n-chunks)
#define K2C  7
#define ASTR 120           // smem row stride (bf16): 60 words -> conflict-free
#define N2   256

// smem byte offsets, kernel 1  (total 197,120 B)
#define K1_W1H 0                    // 112*280*2 = 62720
#define K1_W1L 62720
#define K1_XH  125440               // 64*280*2 = 35840
#define K1_XL  161280
#define K1_SMEM 197120

// smem byte offsets, kernel 2  (total 154,368 B)
#define K2_W2H 0                    // 256*120*2 = 61440
#define K2_W2L 61440
#define K2_AH  122880               // 64*120*2 = 15360
#define K2_AL  138240
#define K2_R2  153600               // 2*64 floats
#define K2_SC  154112               // 64 floats
#define K2_SMEM 154368

// hidden activations, split bf16 hi/lo planes (scratch allowed via __device__ globals)
__device__ __nv_bfloat16 g_Hhi[(size_t)BMAX * N1];
__device__ __nv_bfloat16 g_Hlo[(size_t)BMAX * N1];

__device__ __forceinline__ void mma16816(float c[4], const uint32_t a[4],
                                         uint32_t b0, uint32_t b1)
{
    asm volatile(
        "mma.sync.aligned.m16n8k16.row.col.f32.bf16.bf16.f32 "
        "{%0,%1,%2,%3},{%4,%5,%6,%7},{%8,%9},{%0,%1,%2,%3};"
        : "+f"(c[0]), "+f"(c[1]), "+f"(c[2]), "+f"(c[3])
        : "r"(a[0]), "r"(a[1]), "r"(a[2]), "r"(a[3]), "r"(b0), "r"(b1));
}

__device__ __forceinline__ uint32_t ldw(const __nv_bfloat16* p) {
    return *reinterpret_cast<const uint32_t*>(p);
}

__device__ __forceinline__ void split_bf16(float v, __nv_bfloat16& hi, __nv_bfloat16& lo) {
    hi = __float2bfloat16(v);
    lo = __float2bfloat16(v - __bfloat162float(hi));
}

// ---------------------------------------------------------------------------
// Kernel 1: H = tanh([t,z] @ W1 + b1), stored as bf16 hi/lo planes [B x 112]
// ---------------------------------------------------------------------------
__global__ void __launch_bounds__(256, 1)
k1_hidden(const float* __restrict__ z, const float* __restrict__ t,
          const float* __restrict__ W1, const float* __restrict__ b1, int B)
{
    extern __shared__ char sm[];
    __nv_bfloat16* W1H = (__nv_bfloat16*)(sm + K1_W1H);  // [112][280] W1T[n][k]
    __nv_bfloat16* W1L = (__nv_bfloat16*)(sm + K1_W1L);
    __nv_bfloat16* XH  = (__nv_bfloat16*)(sm + K1_XH);   // [64][280]  features
    __nv_bfloat16* XL  = (__nv_bfloat16*)(sm + K1_XL);

    const int tid  = threadIdx.x;
    const int lane = tid & 31;
    const int w    = tid >> 5;
    const int rg   = w & 3;        // row group: rows rg*16 .. rg*16+15
    const int nh   = w >> 2;       // n-half: 7 n-chunks each (14 total)

    // zero weight planes (covers n>=100 rows and k>=257 cols)
    for (int i = tid; i < N1 * XSTR / 2; i += 256) {
        ((uint32_t*)W1H)[i] = 0u;
        ((uint32_t*)W1L)[i] = 0u;
    }
    __syncthreads();
    // fill W1T[n][k] = W1[k*100+n], split hi/lo
    for (int i = tid; i < 257 * HH; i += 256) {
        int k = i / HH, n = i % HH;
        __nv_bfloat16 hi, lo;
        split_bf16(W1[i], hi, lo);
        W1H[n * XSTR + k] = hi;
        W1L[n * XSTR + k] = lo;
    }
    // zero feature pad cols 257..271 once (tile loads never touch them)
    for (int i = tid; i < MT * 15; i += 256) {
        int r = i / 15, c = 257 + i % 15;
        XH[r * XSTR + c] = __float2bfloat16(0.f);
        XL[r * XSTR + c] = __float2bfloat16(0.f);
    }

    const int nTiles = B / MT;
    const int m0   = rg * 16;
    const int arow = m0 + (lane >> 2);
    const int koff = 2 * (lane & 3);

    for (int tile = blockIdx.x; tile < nTiles; tile += gridDim.x) {
        const int row0 = tile * MT;
        __syncthreads();   // previous tile's MMA readers done

        // stage features: col 0 = t, cols 1..256 = z (coalesced)
        for (int i = tid; i < MT * DD; i += 256) {
            int r = i >> 8, c = i & 255;
            __nv_bfloat16 hi, lo;
            split_bf16(z[(size_t)(row0 + r) * DD + c], hi, lo);
            XH[r * XSTR + 1 + c] = hi;
            XL[r * XSTR + 1 + c] = lo;
        }
        if (tid < MT) {
            __nv_bfloat16 hi, lo;
            split_bf16(t[row0 + tid], hi, lo);
            XH[tid * XSTR] = hi;
            XL[tid * XSTR] = lo;
        }
        __syncthreads();

        float C[7][4];
        #pragma unroll
        for (int j = 0; j < 7; j++)
            #pragma unroll
            for (int q = 0; q < 4; q++) C[j][q] = 0.f;

        for (int kc = 0; kc < K1C; kc++) {
            const int k0 = kc * 16;
            const __nv_bfloat16* xh = XH + arow * XSTR + k0 + koff;
            const __nv_bfloat16* xl = XL + arow * XSTR + k0 + koff;
            uint32_t ah[4] = { ldw(xh), ldw(xh + 8 * XSTR), ldw(xh + 8), ldw(xh + 8 * XSTR + 8) };
            uint32_t al[4] = { ldw(xl), ldw(xl + 8 * XSTR), ldw(xl + 8), ldw(xl + 8 * XSTR + 8) };
            #pragma unroll
            for (int j = 0; j < 7; j++) {
                const int n0 = (nh * 7 + j) * 8;
                const __nv_bfloat16* bh = W1H + (n0 + (lane >> 2)) * XSTR + k0 + koff;
                const __nv_bfloat16* bl = W1L + (n0 + (lane >> 2)) * XSTR + k0 + koff;
                uint32_t bh0 = ldw(bh), bh1 = ldw(bh + 8);
                uint32_t bl0 = ldw(bl), bl1 = ldw(bl + 8);
                mma16816(C[j], ah, bh0, bh1);   // hi*hi
                mma16816(C[j], ah, bl0, bl1);   // hi*lo
                mma16816(C[j], al, bh0, bh1);   // lo*hi
            }
        }

        // epilogue: bias + tanh + bf16 hi/lo split store
        const int gr0 = row0 + m0 + (lane >> 2);
        #pragma unroll
        for (int j = 0; j < 7; j++) {
            const int col = (nh * 7 + j) * 8 + 2 * (lane & 3);
            const float be = (col     < HH) ? b1[col]     : 0.f;
            const float bo = (col + 1 < HH) ? b1[col + 1] : 0.f;
            float v00 = tanhf(C[j][0] + be), v01 = tanhf(C[j][1] + bo);
            float v10 = tanhf(C[j][2] + be), v11 = tanhf(C[j][3] + bo);
            __nv_bfloat16 h0, l0, h1, l1;
            // row gr0
            split_bf16(v00, h0, l0); split_bf16(v01, h1, l1);
            { __nv_bfloat162 ph; ph.x = h0; ph.y = h1;
              *reinterpret_cast<__nv_bfloat162*>(&g_Hhi[(size_t)gr0 * N1 + col]) = ph;
              __nv_bfloat162 pl; pl.x = l0; pl.y = l1;
              *reinterpret_cast<__nv_bfloat162*>(&g_Hlo[(size_t)gr0 * N1 + col]) = pl; }
            // row gr0 + 8
            split_bf16(v10, h0, l0); split_bf16(v11, h1, l1);
            { __nv_bfloat162 ph; ph.x = h0; ph.y = h1;
              *reinterpret_cast<__nv_bfloat162*>(&g_Hhi[(size_t)(gr0 + 8) * N1 + col]) = ph;
              __nv_bfloat162 pl; pl.x = l0; pl.y = l1;
              *reinterpret_cast<__nv_bfloat162*>(&g_Hlo[(size_t)(gr0 + 8) * N1 + col]) = pl; }
        }
    }
}

// ---------------------------------------------------------------------------
// Kernel 2: P = H @ W2 + b2; LambertW scale; out = -scale * P
// ---------------------------------------------------------------------------
__global__ void __launch_bounds__(256, 1)
k2_output(const float* __restrict__ W2, const float* __restrict__ b2,
          float* __restrict__ out, int B)
{
    extern __shared__ char sm[];
    __nv_bfloat16* W2H = (__nv_bfloat16*)(sm + K2_W2H);  // [256][120] W2T[n][k]
    __nv_bfloat16* W2L = (__nv_bfloat16*)(sm + K2_W2L);
    __nv_bfloat16* AH  = (__nv_bfloat16*)(sm + K2_AH);   // [64][120]
    __nv_bfloat16* AL  = (__nv_bfloat16*)(sm + K2_AL);
    float* R2 = (float*)(sm + K2_R2);                    // [2][64]
    float* SC = (float*)(sm + K2_SC);                    // [64]

    const int tid  = threadIdx.x;
    const int lane = tid & 31;
    const int w    = tid >> 5;
    const int rg   = w & 3;
    const int nh   = w >> 2;       // 16 n-chunks each

    for (int i = tid; i < N2 * ASTR / 2; i += 256) {
        ((uint32_t*)W2H)[i] = 0u;
        ((uint32_t*)W2L)[i] = 0u;
    }
    __syncthreads();
    for (int i = tid; i < HH * N2; i += 256) {
        int k = i >> 8, n = i & 255;
        __nv_bfloat16 hi, lo;
        split_bf16(W2[i], hi, lo);
        W2H[n * ASTR + k] = hi;
        W2L[n * ASTR + k] = lo;
    }

    const int nTiles = B / MT;
    const int m0   = rg * 16;
    const int arow = m0 + (lane >> 2);
    const int koff = 2 * (lane & 3);

    for (int tile = blockIdx.x; tile < nTiles; tile += gridDim.x) {
        const int row0 = tile * MT;
        __syncthreads();

        // stage A tile (bf16 planes, packed word copies; cols 0..111 valid)
        for (int i = tid; i < MT * (N1 / 2); i += 256) {
            int r = i / (N1 / 2), cp = (i % (N1 / 2)) * 2;
            *(uint32_t*)&AH[r * ASTR + cp] =
                *(const uint32_t*)&g_Hhi[(size_t)(row0 + r) * N1 + cp];
            *(uint32_t*)&AL[r * ASTR + cp] =
                *(const uint32_t*)&g_Hlo[(size_t)(row0 + r) * N1 + cp];
        }
        __syncthreads();

        float C[16][4];
        #pragma unroll
        for (int j = 0; j < 16; j++)
            #pragma unroll
            for (int q = 0; q < 4; q++) C[j][q] = 0.f;

        for (int kc = 0; kc < K2C; kc++) {
            const int k0 = kc * 16;
            const __nv_bfloat16* xh = AH + arow * ASTR + k0 + koff;
            const __nv_bfloat16* xl = AL + arow * ASTR + k0 + koff;
            uint32_t ah[4] = { ldw(xh), ldw(xh + 8 * ASTR), ldw(xh + 8), ldw(xh + 8 * ASTR + 8) };
            uint32_t al[4] = { ldw(xl), ldw(xl + 8 * ASTR), ldw(xl + 8), ldw(xl + 8 * ASTR + 8) };
            #pragma unroll
            for (int j = 0; j < 16; j++) {
                const int n0 = (nh * 16 + j) * 8;
                const __nv_bfloat16* bh = W2H + (n0 + (lane >> 2)) * ASTR + k0 + koff;
                const __nv_bfloat16* bl = W2L + (n0 + (lane >> 2)) * ASTR + k0 + koff;
                uint32_t bh0 = ldw(bh), bh1 = ldw(bh + 8);
                uint32_t bl0 = ldw(bl), bl1 = ldw(bl + 8);
                mma16816(C[j], ah, bh0, bh1);
                mma16816(C[j], ah, bl0, bl1);
                mma16816(C[j], al, bh0, bh1);
            }
        }

        // bias + per-row sum of squares
        float sq0 = 0.f, sq1 = 0.f;
        #pragma unroll
        for (int j = 0; j < 16; j++) {
            const int col = (nh * 16 + j) * 8 + 2 * (lane & 3);
            const float be = b2[col], bo = b2[col + 1];
            C[j][0] += be; C[j][1] += bo;
            C[j][2] += be; C[j][3] += bo;
            sq0 += C[j][0] * C[j][0] + C[j][1] * C[j][1];
            sq1 += C[j][2] * C[j][2] + C[j][3] * C[j][3];
        }
        sq0 += __shfl_xor_sync(0xffffffffu, sq0, 1);
        sq0 += __shfl_xor_sync(0xffffffffu, sq0, 2);
        sq1 += __shfl_xor_sync(0xffffffffu, sq1, 1);
        sq1 += __shfl_xor_sync(0xffffffffu, sq1, 2);
        if ((lane & 3) == 0) {
            const int lr = m0 + (lane >> 2);
            R2[nh * 64 + lr]     = sq0;
            R2[nh * 64 + lr + 8] = sq1;
        }
        __syncthreads();

        if (tid < MT) {
            float r2 = R2[tid] + R2[64 + tid];
            float wv = log1pf(r2);
            #pragma unroll
            for (int it = 0; it < 10; it++) {
                float ew = __expf(wv);
                wv = wv - (wv * ew - r2) / ((1.f + wv) * ew);
            }
            wv = fmaxf(wv, 0.f);
            float tn = sqrtf(wv);
            float rr = sqrtf(r2);
            SC[tid] = (rr > 1e-12f) ? tn / fmaxf(rr, 1e-12f) : 1.0f;
        }
        __syncthreads();

        const int lr0 = m0 + (lane >> 2);
        const float s0 = SC[lr0], s1 = SC[lr0 + 8];
        #pragma unroll
        for (int j = 0; j < 16; j++) {
            const int col = (nh * 16 + j) * 8 + 2 * (lane & 3);
            float2 o0; o0.x = -s0 * C[j][0]; o0.y = -s0 * C[j][1];
            *reinterpret_cast<float2*>(&out[(size_t)(row0 + lr0) * DD + col]) = o0;
            float2 o1; o1.x = -s1 * C[j][2]; o1.y = -s1 * C[j][3];
            *reinterpret_cast<float2*>(&out[(size_t)(row0 + lr0 + 8) * DD + col]) = o1;
        }
    }
}

extern "C" void kernel_launch(void* const* d_in, const int* in_sizes, int n_in,
                              void* d_out, int out_size)
{
    const float* z  = (const float*)d_in[0];
    const float* t  = (const float*)d_in[1];
    const float* W1 = (const float*)d_in[2];
    const float* b1 = (const float*)d_in[3];
    const float* W2 = (const float*)d_in[4];
    const float* b2 = (const float*)d_in[5];
    float* out = (float*)d_out;
    const int B = in_sizes[1];   // t has B elements

    cudaFuncSetAttribute(k1_hidden, cudaFuncAttributeMaxDynamicSharedMemorySize, K1_SMEM);
    cudaFuncSetAttribute(k2_output, cudaFuncAttributeMaxDynamicSharedMemorySize, K2_SMEM);

    k1_hidden<<<148, 256, K1_SMEM>>>(z, t, W1, b1, B);
    k2_output<<<148, 256, K2_SMEM>>>(W2, b2, out, B);
}

// round 5
// speedup vs baseline: 2.7881x; 1.0923x over previous
#include <cuda_runtime.h>
#include <cuda_bf16.h>
#include <math.h>
#include <stdint.h>

// Shapes (fixed by dataset): B=131072, D=256, H=100
#define BMAX 131072
#define DD   256
#define HH   100
#define MT   64            // batch rows per tile
#define BDIM 512           // 16 warps -> 4 per SMSP (was 8 -> issue-bound at 20%)

// Kernel 1 (layer 1): K = 257 -> pad 272 (17 k-chunks), N = 100 -> pad 112 (14 n-chunks)
#define K1C  17
#define XSTR 280           // smem row stride (bf16): 140 words; banks 12r+c bijective -> conflict-free
#define N1   112

// Kernel 2 (layer 2): K = 112 (7 k-chunks), N = 256 (32 n-chunks)
#define K2C  7
#define ASTR 120           // smem row stride (bf16): 60 words; banks 28r+c bijective -> conflict-free
#define N2   256

// smem byte offsets, kernel 1  (total 197,120 B)
#define K1_W1H 0                    // 112*280*2 = 62720
#define K1_W1L 62720
#define K1_XH  125440               // 64*280*2 = 35840
#define K1_XL  161280
#define K1_SMEM 197120

// smem byte offsets, kernel 2  (total 154,880 B)
#define K2_W2H 0                    // 256*120*2 = 61440
#define K2_W2L 61440
#define K2_AH  122880               // 64*120*2 = 15360
#define K2_AL  138240
#define K2_R2  153600               // 4*64 floats = 1024
#define K2_SC  154624               // 64 floats
#define K2_SMEM 154880

// hidden activations, split bf16 hi/lo planes (scratch via __device__ globals)
__device__ __nv_bfloat16 g_Hhi[(size_t)BMAX * N1];
__device__ __nv_bfloat16 g_Hlo[(size_t)BMAX * N1];

__device__ __forceinline__ void mma16816(float c[4], const uint32_t a[4],
                                         uint32_t b0, uint32_t b1)
{
    asm volatile(
        "mma.sync.aligned.m16n8k16.row.col.f32.bf16.bf16.f32 "
        "{%0,%1,%2,%3},{%4,%5,%6,%7},{%8,%9},{%0,%1,%2,%3};"
        : "+f"(c[0]), "+f"(c[1]), "+f"(c[2]), "+f"(c[3])
        : "r"(a[0]), "r"(a[1]), "r"(a[2]), "r"(a[3]), "r"(b0), "r"(b1));
}

__device__ __forceinline__ uint32_t ldw(const __nv_bfloat16* p) {
    return *reinterpret_cast<const uint32_t*>(p);
}

__device__ __forceinline__ void split_bf16(float v, __nv_bfloat16& hi, __nv_bfloat16& lo) {
    hi = __float2bfloat16(v);
    lo = __float2bfloat16(v - __bfloat162float(hi));
}

// ---------------------------------------------------------------------------
// Kernel 1: H = tanh([t,z] @ W1 + b1), stored as bf16 hi/lo planes [B x 112]
// ---------------------------------------------------------------------------
__global__ void __launch_bounds__(BDIM, 1)
k1_hidden(const float* __restrict__ z, const float* __restrict__ t,
          const float* __restrict__ W1, const float* __restrict__ b1, int B)
{
    extern __shared__ char sm[];
    __nv_bfloat16* W1H = (__nv_bfloat16*)(sm + K1_W1H);  // [112][280] W1T[n][k]
    __nv_bfloat16* W1L = (__nv_bfloat16*)(sm + K1_W1L);
    __nv_bfloat16* XH  = (__nv_bfloat16*)(sm + K1_XH);   // [64][280]  features
    __nv_bfloat16* XL  = (__nv_bfloat16*)(sm + K1_XL);

    const int tid  = threadIdx.x;
    const int lane = tid & 31;
    const int w    = tid >> 5;
    const int rg   = w & 3;              // row group: rows rg*16 .. rg*16+15
    const int nq   = w >> 2;             // n-quarter (0..3)
    const int cstart = nq * 4 - ((nq >= 3) ? 1 : 0);   // {0,4,8,11}
    const int ccount = (nq >= 2) ? 3 : 4;              // {4,4,3,3}

    // zero weight planes (covers n>=100 rows and k>=257 cols)
    for (int i = tid; i < N1 * XSTR / 2; i += BDIM) {
        ((uint32_t*)W1H)[i] = 0u;
        ((uint32_t*)W1L)[i] = 0u;
    }
    __syncthreads();
    // fill W1T[n][k] = W1[k*100+n], split hi/lo
    for (int i = tid; i < 257 * HH; i += BDIM) {
        int k = i / HH, n = i % HH;
        __nv_bfloat16 hi, lo;
        split_bf16(W1[i], hi, lo);
        W1H[n * XSTR + k] = hi;
        W1L[n * XSTR + k] = lo;
    }
    // zero feature pad cols 257..271 once (tile loads never touch them)
    for (int i = tid; i < MT * 15; i += BDIM) {
        int r = i / 15, c = 257 + i % 15;
        XH[r * XSTR + c] = __float2bfloat16(0.f);
        XL[r * XSTR + c] = __float2bfloat16(0.f);
    }

    const int nTiles = B / MT;
    const int m0   = rg * 16;
    const int arow = m0 + (lane >> 2);
    const int koff = 2 * (lane & 3);

    for (int tile = blockIdx.x; tile < nTiles; tile += gridDim.x) {
        const int row0 = tile * MT;
        __syncthreads();   // previous tile's MMA readers done

        // stage features: col 0 = t, cols 1..256 = z (coalesced)
        for (int i = tid; i < MT * DD; i += BDIM) {
            int r = i >> 8, c = i & 255;
            __nv_bfloat16 hi, lo;
            split_bf16(z[(size_t)(row0 + r) * DD + c], hi, lo);
            XH[r * XSTR + 1 + c] = hi;
            XL[r * XSTR + 1 + c] = lo;
        }
        if (tid < MT) {
            __nv_bfloat16 hi, lo;
            split_bf16(t[row0 + tid], hi, lo);
            XH[tid * XSTR] = hi;
            XL[tid * XSTR] = lo;
        }
        __syncthreads();

        float C[4][4];
        #pragma unroll
        for (int j = 0; j < 4; j++)
            #pragma unroll
            for (int q = 0; q < 4; q++) C[j][q] = 0.f;

        for (int kc = 0; kc < K1C; kc++) {
            const int k0 = kc * 16;
            const __nv_bfloat16* xh = XH + arow * XSTR + k0 + koff;
            const __nv_bfloat16* xl = XL + arow * XSTR + k0 + koff;
            uint32_t ah[4] = { ldw(xh), ldw(xh + 8 * XSTR), ldw(xh + 8), ldw(xh + 8 * XSTR + 8) };
            uint32_t al[4] = { ldw(xl), ldw(xl + 8 * XSTR), ldw(xl + 8), ldw(xl + 8 * XSTR + 8) };
            #pragma unroll
            for (int j = 0; j < 4; j++) {
                if (j < ccount) {
                    const int n0 = (cstart + j) * 8;
                    const __nv_bfloat16* bh = W1H + (n0 + (lane >> 2)) * XSTR + k0 + koff;
                    const __nv_bfloat16* bl = W1L + (n0 + (lane >> 2)) * XSTR + k0 + koff;
                    uint32_t bh0 = ldw(bh), bh1 = ldw(bh + 8);
                    uint32_t bl0 = ldw(bl), bl1 = ldw(bl + 8);
                    mma16816(C[j], ah, bh0, bh1);   // hi*hi
                    mma16816(C[j], ah, bl0, bl1);   // hi*lo
                    mma16816(C[j], al, bh0, bh1);   // lo*hi
                }
            }
        }

        // epilogue: bias + tanh + bf16 hi/lo split store
        const int gr0 = row0 + m0 + (lane >> 2);
        #pragma unroll
        for (int j = 0; j < 4; j++) {
            if (j < ccount) {
                const int col = (cstart + j) * 8 + 2 * (lane & 3);
                const float be = (col     < HH) ? b1[col]     : 0.f;
                const float bo = (col + 1 < HH) ? b1[col + 1] : 0.f;
                float v00 = tanhf(C[j][0] + be), v01 = tanhf(C[j][1] + bo);
                float v10 = tanhf(C[j][2] + be), v11 = tanhf(C[j][3] + bo);
                __nv_bfloat16 h0, l0, h1, l1;
                split_bf16(v00, h0, l0); split_bf16(v01, h1, l1);
                { __nv_bfloat162 ph; ph.x = h0; ph.y = h1;
                  *reinterpret_cast<__nv_bfloat162*>(&g_Hhi[(size_t)gr0 * N1 + col]) = ph;
                  __nv_bfloat162 pl; pl.x = l0; pl.y = l1;
                  *reinterpret_cast<__nv_bfloat162*>(&g_Hlo[(size_t)gr0 * N1 + col]) = pl; }
                split_bf16(v10, h0, l0); split_bf16(v11, h1, l1);
                { __nv_bfloat162 ph; ph.x = h0; ph.y = h1;
                  *reinterpret_cast<__nv_bfloat162*>(&g_Hhi[(size_t)(gr0 + 8) * N1 + col]) = ph;
                  __nv_bfloat162 pl; pl.x = l0; pl.y = l1;
                  *reinterpret_cast<__nv_bfloat162*>(&g_Hlo[(size_t)(gr0 + 8) * N1 + col]) = pl; }
            }
        }
    }
}

// ---------------------------------------------------------------------------
// Kernel 2: P = H @ W2 + b2; LambertW scale; out = -scale * P
// ---------------------------------------------------------------------------
__global__ void __launch_bounds__(BDIM, 1)
k2_output(const float* __restrict__ W2, const float* __restrict__ b2,
          float* __restrict__ out, int B)
{
    extern __shared__ char sm[];
    __nv_bfloat16* W2H = (__nv_bfloat16*)(sm + K2_W2H);  // [256][120] W2T[n][k]
    __nv_bfloat16* W2L = (__nv_bfloat16*)(sm + K2_W2L);
    __nv_bfloat16* AH  = (__nv_bfloat16*)(sm + K2_AH);   // [64][120]
    __nv_bfloat16* AL  = (__nv_bfloat16*)(sm + K2_AL);
    float* R2 = (float*)(sm + K2_R2);                    // [4][64]
    float* SC = (float*)(sm + K2_SC);                    // [64]

    const int tid  = threadIdx.x;
    const int lane = tid & 31;
    const int w    = tid >> 5;
    const int rg   = w & 3;
    const int nq   = w >> 2;           // 8 n-chunks each (32 total)

    for (int i = tid; i < N2 * ASTR / 2; i += BDIM) {
        ((uint32_t*)W2H)[i] = 0u;
        ((uint32_t*)W2L)[i] = 0u;
    }
    __syncthreads();
    for (int i = tid; i < HH * N2; i += BDIM) {
        int k = i >> 8, n = i & 255;
        __nv_bfloat16 hi, lo;
        split_bf16(W2[i], hi, lo);
        W2H[n * ASTR + k] = hi;
        W2L[n * ASTR + k] = lo;
    }

    const int nTiles = B / MT;
    const int m0   = rg * 16;
    const int arow = m0 + (lane >> 2);
    const int koff = 2 * (lane & 3);

    for (int tile = blockIdx.x; tile < nTiles; tile += gridDim.x) {
        const int row0 = tile * MT;
        __syncthreads();

        // stage A tile (bf16 planes, packed word copies; cols 0..111 valid)
        for (int i = tid; i < MT * (N1 / 2); i += BDIM) {
            int r = i / (N1 / 2), cp = (i % (N1 / 2)) * 2;
            *(uint32_t*)&AH[r * ASTR + cp] =
                *(const uint32_t*)&g_Hhi[(size_t)(row0 + r) * N1 + cp];
            *(uint32_t*)&AL[r * ASTR + cp] =
                *(const uint32_t*)&g_Hlo[(size_t)(row0 + r) * N1 + cp];
        }
        __syncthreads();

        float C[8][4];
        #pragma unroll
        for (int j = 0; j < 8; j++)
            #pragma unroll
            for (int q = 0; q < 4; q++) C[j][q] = 0.f;

        for (int kc = 0; kc < K2C; kc++) {
            const int k0 = kc * 16;
            const __nv_bfloat16* xh = AH + arow * ASTR + k0 + koff;
            const __nv_bfloat16* xl = AL + arow * ASTR + k0 + koff;
            uint32_t ah[4] = { ldw(xh), ldw(xh + 8 * ASTR), ldw(xh + 8), ldw(xh + 8 * ASTR + 8) };
            uint32_t al[4] = { ldw(xl), ldw(xl + 8 * ASTR), ldw(xl + 8), ldw(xl + 8 * ASTR + 8) };
            #pragma unroll
            for (int j = 0; j < 8; j++) {
                const int n0 = (nq * 8 + j) * 8;
                const __nv_bfloat16* bh = W2H + (n0 + (lane >> 2)) * ASTR + k0 + koff;
                const __nv_bfloat16* bl = W2L + (n0 + (lane >> 2)) * ASTR + k0 + koff;
                uint32_t bh0 = ldw(bh), bh1 = ldw(bh + 8);
                uint32_t bl0 = ldw(bl), bl1 = ldw(bl + 8);
                mma16816(C[j], ah, bh0, bh1);
                mma16816(C[j], ah, bl0, bl1);
                mma16816(C[j], al, bh0, bh1);
            }
        }

        // bias + per-row sum of squares (partial per n-quarter)
        float sq0 = 0.f, sq1 = 0.f;
        #pragma unroll
        for (int j = 0; j < 8; j++) {
            const int col = (nq * 8 + j) * 8 + 2 * (lane & 3);
            const float be = b2[col], bo = b2[col + 1];
            C[j][0] += be; C[j][1] += bo;
            C[j][2] += be; C[j][3] += bo;
            sq0 += C[j][0] * C[j][0] + C[j][1] * C[j][1];
            sq1 += C[j][2] * C[j][2] + C[j][3] * C[j][3];
        }
        sq0 += __shfl_xor_sync(0xffffffffu, sq0, 1);
        sq0 += __shfl_xor_sync(0xffffffffu, sq0, 2);
        sq1 += __shfl_xor_sync(0xffffffffu, sq1, 1);
        sq1 += __shfl_xor_sync(0xffffffffu, sq1, 2);
        if ((lane & 3) == 0) {
            const int lr = m0 + (lane >> 2);
            R2[nq * 64 + lr]     = sq0;
            R2[nq * 64 + lr + 8] = sq1;
        }
        __syncthreads();

        if (tid < MT) {
            float r2 = R2[tid] + R2[64 + tid] + R2[128 + tid] + R2[192 + tid];
            float wv = log1pf(r2);
            #pragma unroll
            for (int it = 0; it < 10; it++) {
                float ew = __expf(wv);
                wv = wv - (wv * ew - r2) / ((1.f + wv) * ew);
            }
            wv = fmaxf(wv, 0.f);
            float tn = sqrtf(wv);
            float rr = sqrtf(r2);
            SC[tid] = (rr > 1e-12f) ? tn / fmaxf(rr, 1e-12f) : 1.0f;
        }
        __syncthreads();

        const int lr0 = m0 + (lane >> 2);
        const float s0 = SC[lr0], s1 = SC[lr0 + 8];
        #pragma unroll
        for (int j = 0; j < 8; j++) {
            const int col = (nq * 8 + j) * 8 + 2 * (lane & 3);
            float2 o0; o0.x = -s0 * C[j][0]; o0.y = -s0 * C[j][1];
            *reinterpret_cast<float2*>(&out[(size_t)(row0 + lr0) * DD + col]) = o0;
            float2 o1; o1.x = -s1 * C[j][2]; o1.y = -s1 * C[j][3];
            *reinterpret_cast<float2*>(&out[(size_t)(row0 + lr0 + 8) * DD + col]) = o1;
        }
    }
}

extern "C" void kernel_launch(void* const* d_in, const int* in_sizes, int n_in,
                              void* d_out, int out_size)
{
    const float* z  = (const float*)d_in[0];
    const float* t  = (const float*)d_in[1];
    const float* W1 = (const float*)d_in[2];
    const float* b1 = (const float*)d_in[3];
    const float* W2 = (const float*)d_in[4];
    const float* b2 = (const float*)d_in[5];
    float* out = (float*)d_out;
    const int B = in_sizes[1];   // t has B elements

    cudaFuncSetAttribute(k1_hidden, cudaFuncAttributeMaxDynamicSharedMemorySize, K1_SMEM);
    cudaFuncSetAttribute(k2_output, cudaFuncAttributeMaxDynamicSharedMemorySize, K2_SMEM);

    k1_hidden<<<148, BDIM, K1_SMEM>>>(z, t, W1, b1, B);
    k2_output<<<148, BDIM, K2_SMEM>>>(W2, b2, out, B);
}